// round 13
// baseline (speedup 1.0000x reference)
#include <cuda_runtime.h>
#include <math.h>

// Problem constants (validated against in_sizes at launch).
#define NMAX 100000
#define EMAX 3200000
#define FDIM 16
#define KDIM 512

// Scratch (device globals: no allocation allowed).
__device__ __align__(16) float g_dis[NMAX];        // degree -> 1/sqrt(degree)
__device__ __align__(16) float g_hs [NMAX * FDIM]; // h * dis[row] (src-scaled feats)
__device__ __align__(16) float g_agg[NMAX * FDIM]; // accumulator (un-dst-normalized)
__device__ __align__(16) int2  g_eidx[EMAX];       // packed (src, dst) int32
__device__ int g_is64;                             // edge dtype flag (1 = int64)

// ---------------------------------------------------------------------------
// Dtype probe: view edge buffer as int32 words. If words at odd positions are
// all zero over the first 2048 pairs, the data is little-endian int64 (high
// words of indices < 2^31 are 0). Random int32 indices make a false positive
// essentially impossible. Deterministic: same input -> same flag every call.
// ---------------------------------------------------------------------------
__global__ void k_detect(const int* __restrict__ ew, int nwords) {
    __shared__ int any;
    if (threadIdx.x == 0) any = 0;
    __syncthreads();
    int lim = 2048;
    for (int i = threadIdx.x; i < lim; i += blockDim.x) {
        int w = 2 * i + 1;
        if (w < nwords && ew[w] != 0) any = 1;   // benign race: only writes 1
    }
    __syncthreads();
    if (threadIdx.x == 0) g_is64 = (any == 0) ? 1 : 0;
}

// ---------------------------------------------------------------------------
// deg[i] = 1 (self loop) + indegree ; also packs edges -> int2 (clamped).
// ---------------------------------------------------------------------------
__global__ void k_deg_init(int n) {
    int i = blockIdx.x * blockDim.x + threadIdx.x;
    if (i < n) g_dis[i] = 1.0f;
}

__global__ void k_deg_pack(const int* __restrict__ ew, int E, int n) {
    int e = blockIdx.x * blockDim.x + threadIdx.x;
    if (e >= E) return;
    int s, d;
    if (g_is64) {                 // int64 words: value in even int32, high = 0
        s = ew[2 * e];
        d = ew[2 * (e + E)];
    } else {                      // plain int32 layout
        s = ew[e];
        d = ew[e + E];
    }
    // Defensive clamp: an out-of-range index becomes a wrong (measurable)
    // result instead of an illegal access.
    s = min(max(s, 0), n - 1);
    d = min(max(d, 0), n - 1);
    g_eidx[e] = make_int2(s, d);
    atomicAdd(&g_dis[d], 1.0f);
}

__global__ void k_deg_rsqrt(int n) {
    int i = blockIdx.x * blockDim.x + threadIdx.x;
    if (i < n) g_dis[i] = rsqrtf(g_dis[i]);
}

// ---------------------------------------------------------------------------
// GEMM1: h = x @ w1 (100000x512 @ 512x16). Epilogue writes
//   g_hs[r][c] = g_agg[r][c] = h[r][c] * dis[r]
// 256 thr = 8 warps, 4 rows/warp. W transposed in smem, float4 loads.
// ---------------------------------------------------------------------------
__global__ void __launch_bounds__(256) k_gemm1(const float* __restrict__ x,
                                               const float* __restrict__ w1,
                                               int n) {
    __shared__ float Wt[FDIM * KDIM];   // Wt[c*512+k] = w1[k*16+c] (32 KB)
    for (int idx = threadIdx.x; idx < FDIM * KDIM; idx += 256) {
        int k = idx >> 4, c = idx & 15;
        Wt[c * KDIM + k] = w1[idx];
    }
    __syncthreads();

    const int warp = threadIdx.x >> 5;
    const int lane = threadIdx.x & 31;
    const int r0   = (blockIdx.x * 8 + warp) * 4;
    if (r0 >= n) return;

    float acc[4][16];
#pragma unroll
    for (int r = 0; r < 4; r++)
#pragma unroll
        for (int c = 0; c < 16; c++) acc[r][c] = 0.0f;

    const float4* x4 = (const float4*)x;
    const float4* W4 = (const float4*)Wt;

#pragma unroll
    for (int i = 0; i < 4; i++) {
        const int idx = lane + 32 * i;  // float4 index within a 512-float row
        float4 xv[4];
#pragma unroll
        for (int r = 0; r < 4; r++) {
            int row = r0 + r;
            xv[r] = (row < n) ? x4[row * (KDIM / 4) + idx]
                              : make_float4(0.f, 0.f, 0.f, 0.f);
        }
#pragma unroll
        for (int c = 0; c < 16; c++) {
            float4 wv = W4[c * (KDIM / 4) + idx];
#pragma unroll
            for (int r = 0; r < 4; r++) {
                acc[r][c] += xv[r].x * wv.x + xv[r].y * wv.y
                           + xv[r].z * wv.z + xv[r].w * wv.w;
            }
        }
    }

#pragma unroll
    for (int r = 0; r < 4; r++)
#pragma unroll
        for (int c = 0; c < 16; c++) {
            float v = acc[r][c];
            v += __shfl_xor_sync(0xffffffffu, v, 16);
            v += __shfl_xor_sync(0xffffffffu, v, 8);
            v += __shfl_xor_sync(0xffffffffu, v, 4);
            v += __shfl_xor_sync(0xffffffffu, v, 2);
            v += __shfl_xor_sync(0xffffffffu, v, 1);
            acc[r][c] = v;
        }

    if (lane < 16) {
#pragma unroll
        for (int r = 0; r < 4; r++) {
            int row = r0 + r;
            if (row < n) {
                float v = 0.0f;
#pragma unroll
                for (int c = 0; c < 16; c++)
                    if (lane == c) v = acc[r][c];
                float hv = v * g_dis[row];
                g_hs [row * FDIM + lane] = hv;
                g_agg[row * FDIM + lane] = hv;   // self-loop init (pre-dst-norm)
            }
        }
    }
}

// ---------------------------------------------------------------------------
// Scatter: agg[d] += hs[s]   (dst-normalization deferred to consumer)
// 4 threads per edge, each does one red.global.add.v4.f32 (16 B).
// ---------------------------------------------------------------------------
__global__ void k_scatter(int E4) {
    int t = blockIdx.x * blockDim.x + threadIdx.x;
    if (t >= E4) return;
    int e = t >> 2;
    int q = t & 3;
    int2 sd = g_eidx[e];
    float4 v = ((const float4*)g_hs)[sd.x * 4 + q];
    float* p = &g_agg[sd.y * FDIM + q * 4];
    asm volatile("red.global.add.v4.f32 [%0], {%1,%2,%3,%4};"
                 :: "l"(p), "f"(v.x), "f"(v.y), "f"(v.z), "f"(v.w)
                 : "memory");
}

// ---------------------------------------------------------------------------
// Mid: a1 = dis[r]*agg_raw + b1 ; h2 = relu(a1) @ w2 ; re-init:
//   g_hs[r][c] = g_agg[r][c] = h2[r][c] * dis[r]
// One thread per (row,col); block covers 16 whole rows; __syncthreads splits
// the read phase from the in-place overwrite.
// ---------------------------------------------------------------------------
__global__ void __launch_bounds__(256) k_mid(const float* __restrict__ b1,
                                             const float* __restrict__ w2,
                                             int n) {
    int t = blockIdx.x * blockDim.x + threadIdx.x;
    int r = t >> 4, c = t & 15;
    float acc = 0.0f;
    float ds = 0.0f;
    if (r < n) {
        ds = g_dis[r];
#pragma unroll
        for (int k = 0; k < 16; k++) {
            float hv = fmaxf(g_agg[r * FDIM + k] * ds + b1[k], 0.0f);
            acc += hv * w2[k * 16 + c];
        }
    }
    __syncthreads();   // all reads of this block's rows done before overwrite
    if (r < n) {
        float hv = acc * ds;
        g_hs [r * FDIM + c] = hv;
        g_agg[r * FDIM + c] = hv;
    }
}

// ---------------------------------------------------------------------------
// Finish: out = log_softmax(dis[r]*agg_raw + b2). One thread per row.
// ---------------------------------------------------------------------------
__global__ void k_finish(const float* __restrict__ b2,
                         float* __restrict__ out,
                         int n) {
    int r = blockIdx.x * blockDim.x + threadIdx.x;
    if (r >= n) return;
    float ds = g_dis[r];
    float v[16];
    const float4* a4 = (const float4*)g_agg;
#pragma unroll
    for (int j = 0; j < 4; j++) {
        float4 t = a4[r * 4 + j];
        v[j * 4 + 0] = t.x * ds + b2[j * 4 + 0];
        v[j * 4 + 1] = t.y * ds + b2[j * 4 + 1];
        v[j * 4 + 2] = t.z * ds + b2[j * 4 + 2];
        v[j * 4 + 3] = t.w * ds + b2[j * 4 + 3];
    }
    float mx = v[0];
#pragma unroll
    for (int c = 1; c < 16; c++) mx = fmaxf(mx, v[c]);
    float s = 0.0f;
#pragma unroll
    for (int c = 0; c < 16; c++) s += expf(v[c] - mx);
    float lse = mx + logf(s);
    float4* o4 = (float4*)out;
#pragma unroll
    for (int j = 0; j < 4; j++) {
        float4 t;
        t.x = v[j * 4 + 0] - lse;
        t.y = v[j * 4 + 1] - lse;
        t.z = v[j * 4 + 2] - lse;
        t.w = v[j * 4 + 3] - lse;
        o4[r * 4 + j] = t;
    }
}

// ---------------------------------------------------------------------------
extern "C" void kernel_launch(void* const* d_in, const int* in_sizes, int n_in,
                              void* d_out, int out_size) {
    const float* x   = (const float*)d_in[0];
    const int*   ew  = (const int*)d_in[1];     // edge words (int32 view)
    const float* w1  = (const float*)d_in[2];
    const float* b1  = (const float*)d_in[3];
    const float* w2  = (const float*)d_in[4];
    const float* b2  = (const float*)d_in[5];
    float*       out = (float*)d_out;

    int n = in_sizes[0] / KDIM;            // 100000
    int E = in_sizes[1] / 2;               // 3200000 (element count same for
    if (n > NMAX) n = NMAX;                //          int32 and int64)
    if (E > EMAX) E = EMAX;

    int nb_n   = (n + 255) / 256;
    int nb_e   = (E + 255) / 256;
    int nb_s   = (4 * E + 255) / 256;
    int nb_g   = (n + 31) / 32;            // 32 rows per block
    int nb_mid = (n * 16 + 255) / 256;

    k_detect    <<<1, 256>>>(ew, 2 * E);       // int32 vs int64 probe
    k_deg_init  <<<nb_n, 256>>>(n);
    k_deg_pack  <<<nb_e, 256>>>(ew, E, n);     // indegree + int2 pack
    k_deg_rsqrt <<<nb_n, 256>>>(n);

    k_gemm1     <<<nb_g, 256>>>(x, w1, n);     // h1, self-loop agg init
    k_scatter   <<<nb_s, 256>>>(4 * E);        // layer-1 edge aggregation

    k_mid       <<<nb_mid, 256>>>(b1, w2, n);  // relu + 16x16 GEMM + re-init
    k_scatter   <<<nb_s, 256>>>(4 * E);        // layer-2 edge aggregation

    k_finish    <<<nb_n, 256>>>(b2, out, n);   // +b2, log_softmax
}

// round 16
// speedup vs baseline: 1.0272x; 1.0272x over previous
#include <cuda_runtime.h>
#include <math.h>

// Problem constants (validated against in_sizes at launch).
#define NMAX 100000
#define EMAX 3200000
#define FDIM 16
#define KDIM 512

// Scratch (device globals: no allocation allowed).
__device__ __align__(16) float g_dis[NMAX];        // 1/sqrt(1+indegree)
__device__ __align__(16) float g_hs [NMAX * FDIM]; // h * dis[row]
__device__ __align__(16) float g_agg[NMAX * FDIM]; // pull-gather output (pre-dst-norm)
__device__ __align__(16) int2  g_eidx[EMAX];       // packed (src, dst) int32
__device__ int g_cnt[NMAX];                        // indegree counts
__device__ int g_rowptr[NMAX + 1];                 // CSR row pointers (by dst)
__device__ int g_cursor[NMAX];                     // fill cursors
__device__ int g_csr[EMAX];                        // CSR src indices
__device__ int g_bsum[512];                        // block sums for scan
__device__ int g_is64;                             // edge dtype flag (1 = int64)

// ---------------------------------------------------------------------------
// Dtype probe (validated by the R13 pass): odd int32 words all zero over the
// first 2048 pairs => little-endian int64 indices.
// ---------------------------------------------------------------------------
__global__ void k_detect(const int* __restrict__ ew, int nwords) {
    __shared__ int any;
    if (threadIdx.x == 0) any = 0;
    __syncthreads();
    for (int i = threadIdx.x; i < 2048; i += blockDim.x) {
        int w = 2 * i + 1;
        if (w < nwords && ew[w] != 0) any = 1;
    }
    __syncthreads();
    if (threadIdx.x == 0) g_is64 = (any == 0) ? 1 : 0;
}

__global__ void k_zero(int n) {
    int i = blockIdx.x * blockDim.x + threadIdx.x;
    if (i < n) g_cnt[i] = 0;
}

// Count indegree + pack edges to int2 (clamped).
__global__ void k_count(const int* __restrict__ ew, int E, int n) {
    int e = blockIdx.x * blockDim.x + threadIdx.x;
    if (e >= E) return;
    int s, d;
    if (g_is64) { s = ew[2 * e]; d = ew[2 * (e + E)]; }
    else        { s = ew[e];     d = ew[e + E]; }
    s = min(max(s, 0), n - 1);
    d = min(max(d, 0), n - 1);
    g_eidx[e] = make_int2(s, d);
    atomicAdd(&g_cnt[d], 1);
}

// ---- three-phase exclusive scan of g_cnt -> g_rowptr (+cursor, +dis) ------
__global__ void k_scan1(int n) {            // per-block sums
    __shared__ int sm[256];
    int i = blockIdx.x * 256 + threadIdx.x;
    sm[threadIdx.x] = (i < n) ? g_cnt[i] : 0;
    __syncthreads();
    for (int off = 128; off > 0; off >>= 1) {
        if (threadIdx.x < off) sm[threadIdx.x] += sm[threadIdx.x + off];
        __syncthreads();
    }
    if (threadIdx.x == 0) g_bsum[blockIdx.x] = sm[0];
}

__global__ void k_scan2(int nb) {           // exclusive scan of block sums
    __shared__ int sm[512];
    int t = threadIdx.x;
    sm[t] = (t < nb) ? g_bsum[t] : 0;
    __syncthreads();
    for (int off = 1; off < 512; off <<= 1) {
        int v = (t >= off) ? sm[t - off] : 0;
        __syncthreads();
        sm[t] += v;
        __syncthreads();
    }
    int ex = (t == 0) ? 0 : sm[t - 1];
    if (t < nb) g_bsum[t] = ex;
}

__global__ void k_scan3(int n, int E) {     // local scan + base; rowptr/cursor/dis
    __shared__ int sm[256];
    int t = threadIdx.x;
    int i = blockIdx.x * 256 + t;
    int c = (i < n) ? g_cnt[i] : 0;
    sm[t] = c;
    __syncthreads();
    for (int off = 1; off < 256; off <<= 1) {
        int v = (t >= off) ? sm[t - off] : 0;
        __syncthreads();
        sm[t] += v;
        __syncthreads();
    }
    int ex = (t == 0) ? 0 : sm[t - 1];
    if (i < n) {
        int rp = g_bsum[blockIdx.x] + ex;
        g_rowptr[i] = rp;
        g_cursor[i] = rp;
        g_dis[i] = rsqrtf(1.0f + (float)c);
    }
    if (i == 0) g_rowptr[n] = E;
}

// CSR fill: slot order within a row is atomic-cursor order (fp-sum noise ok).
__global__ void k_fill(int E) {
    int e = blockIdx.x * blockDim.x + threadIdx.x;
    if (e >= E) return;
    int2 sd = g_eidx[e];
    int pos = atomicAdd(&g_cursor[sd.y], 1);
    g_csr[pos] = sd.x;
}

// ---------------------------------------------------------------------------
// GEMM1: h = x @ w1; epilogue writes g_hs[r][c] = h[r][c] * dis[r] only.
// ---------------------------------------------------------------------------
__global__ void __launch_bounds__(256) k_gemm1(const float* __restrict__ x,
                                               const float* __restrict__ w1,
                                               int n) {
    __shared__ float Wt[FDIM * KDIM];
    for (int idx = threadIdx.x; idx < FDIM * KDIM; idx += 256) {
        int k = idx >> 4, c = idx & 15;
        Wt[c * KDIM + k] = w1[idx];
    }
    __syncthreads();

    const int warp = threadIdx.x >> 5;
    const int lane = threadIdx.x & 31;
    const int r0   = (blockIdx.x * 8 + warp) * 4;
    if (r0 >= n) return;

    float acc[4][16];
#pragma unroll
    for (int r = 0; r < 4; r++)
#pragma unroll
        for (int c = 0; c < 16; c++) acc[r][c] = 0.0f;

    const float4* x4 = (const float4*)x;
    const float4* W4 = (const float4*)Wt;

#pragma unroll
    for (int i = 0; i < 4; i++) {
        const int idx = lane + 32 * i;
        float4 xv[4];
#pragma unroll
        for (int r = 0; r < 4; r++) {
            int row = r0 + r;
            xv[r] = (row < n) ? x4[row * (KDIM / 4) + idx]
                              : make_float4(0.f, 0.f, 0.f, 0.f);
        }
#pragma unroll
        for (int c = 0; c < 16; c++) {
            float4 wv = W4[c * (KDIM / 4) + idx];
#pragma unroll
            for (int r = 0; r < 4; r++) {
                acc[r][c] += xv[r].x * wv.x + xv[r].y * wv.y
                           + xv[r].z * wv.z + xv[r].w * wv.w;
            }
        }
    }

#pragma unroll
    for (int r = 0; r < 4; r++)
#pragma unroll
        for (int c = 0; c < 16; c++) {
            float v = acc[r][c];
            v += __shfl_xor_sync(0xffffffffu, v, 16);
            v += __shfl_xor_sync(0xffffffffu, v, 8);
            v += __shfl_xor_sync(0xffffffffu, v, 4);
            v += __shfl_xor_sync(0xffffffffu, v, 2);
            v += __shfl_xor_sync(0xffffffffu, v, 1);
            acc[r][c] = v;
        }

    if (lane < 16) {
#pragma unroll
        for (int r = 0; r < 4; r++) {
            int row = r0 + r;
            if (row < n) {
                float v = 0.0f;
#pragma unroll
                for (int c = 0; c < 16; c++)
                    if (lane == c) v = acc[r][c];
                g_hs[row * FDIM + lane] = v * g_dis[row];
            }
        }
    }
}

// ---------------------------------------------------------------------------
// Pull-gather: agg[r] = hs[r] (self loop) + sum over CSR edges hs[src].
// 4 threads per node; quad broadcasts csr index, gathers float4. No atomics.
// ---------------------------------------------------------------------------
__global__ void __launch_bounds__(256) k_gather(int n) {
    int t = blockIdx.x * 256 + threadIdx.x;
    int r = t >> 2;
    if (r >= n) return;
    int q = t & 3;
    const float4* hs4 = (const float4*)g_hs;
    float4 acc = hs4[r * 4 + q];             // self-loop term
    int idx = g_rowptr[r];
    int end = g_rowptr[r + 1];
    for (; idx + 3 < end; idx += 4) {
        int s0 = g_csr[idx], s1 = g_csr[idx + 1];
        int s2 = g_csr[idx + 2], s3 = g_csr[idx + 3];
        float4 v0 = hs4[s0 * 4 + q];
        float4 v1 = hs4[s1 * 4 + q];
        float4 v2 = hs4[s2 * 4 + q];
        float4 v3 = hs4[s3 * 4 + q];
        acc.x += (v0.x + v1.x) + (v2.x + v3.x);
        acc.y += (v0.y + v1.y) + (v2.y + v3.y);
        acc.z += (v0.z + v1.z) + (v2.z + v3.z);
        acc.w += (v0.w + v1.w) + (v2.w + v3.w);
    }
    for (; idx < end; idx++) {
        int s = g_csr[idx];
        float4 v = hs4[s * 4 + q];
        acc.x += v.x; acc.y += v.y; acc.z += v.z; acc.w += v.w;
    }
    ((float4*)g_agg)[r * 4 + q] = acc;
}

// ---------------------------------------------------------------------------
// Mid: h2 = relu(dis[r]*agg + b1) @ w2 ; writes g_hs = h2*dis (no hazard:
// reads g_agg only, writes g_hs only).
// ---------------------------------------------------------------------------
__global__ void __launch_bounds__(256) k_mid(const float* __restrict__ b1,
                                             const float* __restrict__ w2,
                                             int n) {
    int t = blockIdx.x * blockDim.x + threadIdx.x;
    int r = t >> 4, c = t & 15;
    if (r >= n) return;
    float ds = g_dis[r];
    float acc = 0.0f;
#pragma unroll
    for (int k = 0; k < 16; k++) {
        float hv = fmaxf(g_agg[r * FDIM + k] * ds + b1[k], 0.0f);
        acc += hv * w2[k * 16 + c];
    }
    g_hs[r * FDIM + c] = acc * ds;
}

// ---------------------------------------------------------------------------
// Finish: out = log_softmax(dis[r]*agg + b2). One thread per row.
// ---------------------------------------------------------------------------
__global__ void k_finish(const float* __restrict__ b2,
                         float* __restrict__ out,
                         int n) {
    int r = blockIdx.x * blockDim.x + threadIdx.x;
    if (r >= n) return;
    float ds = g_dis[r];
    float v[16];
    const float4* a4 = (const float4*)g_agg;
#pragma unroll
    for (int j = 0; j < 4; j++) {
        float4 t = a4[r * 4 + j];
        v[j * 4 + 0] = t.x * ds + b2[j * 4 + 0];
        v[j * 4 + 1] = t.y * ds + b2[j * 4 + 1];
        v[j * 4 + 2] = t.z * ds + b2[j * 4 + 2];
        v[j * 4 + 3] = t.w * ds + b2[j * 4 + 3];
    }
    float mx = v[0];
#pragma unroll
    for (int c = 1; c < 16; c++) mx = fmaxf(mx, v[c]);
    float s = 0.0f;
#pragma unroll
    for (int c = 0; c < 16; c++) s += expf(v[c] - mx);
    float lse = mx + logf(s);
    float4* o4 = (float4*)out;
#pragma unroll
    for (int j = 0; j < 4; j++) {
        float4 t;
        t.x = v[j * 4 + 0] - lse;
        t.y = v[j * 4 + 1] - lse;
        t.z = v[j * 4 + 2] - lse;
        t.w = v[j * 4 + 3] - lse;
        o4[r * 4 + j] = t;
    }
}

// ---------------------------------------------------------------------------
extern "C" void kernel_launch(void* const* d_in, const int* in_sizes, int n_in,
                              void* d_out, int out_size) {
    const float* x   = (const float*)d_in[0];
    const int*   ew  = (const int*)d_in[1];     // edge words (int32 view)
    const float* w1  = (const float*)d_in[2];
    const float* b1  = (const float*)d_in[3];
    const float* w2  = (const float*)d_in[4];
    const float* b2  = (const float*)d_in[5];
    float*       out = (float*)d_out;

    int n = in_sizes[0] / KDIM;            // 100000
    int E = in_sizes[1] / 2;               // 3200000
    if (n > NMAX) n = NMAX;
    if (E > EMAX) E = EMAX;

    int nb_n   = (n + 255) / 256;          // 391 (must be <= 512 for scan2)
    int nb_e   = (E + 255) / 256;
    int nb_g   = (n + 31) / 32;
    int nb_q   = (4 * n + 255) / 256;      // gather: 4 threads per node
    int nb_mid = (n * 16 + 255) / 256;

    k_detect <<<1, 256>>>(ew, 2 * E);
    k_zero   <<<nb_n, 256>>>(n);
    k_count  <<<nb_e, 256>>>(ew, E, n);

    k_scan1  <<<nb_n, 256>>>(n);
    k_scan2  <<<1, 512>>>(nb_n);
    k_scan3  <<<nb_n, 256>>>(n, E);
    k_fill   <<<nb_e, 256>>>(E);

    k_gemm1  <<<nb_g, 256>>>(x, w1, n);
    k_gather <<<nb_q, 256>>>(n);           // layer-1 aggregation (pull)

    k_mid    <<<nb_mid, 256>>>(b1, w2, n);
    k_gather <<<nb_q, 256>>>(n);           // layer-2 aggregation (pull)

    k_finish <<<nb_n, 256>>>(b2, out, n);
}